// round 15
// baseline (speedup 1.0000x reference)
#include <cuda_runtime.h>
#include <cuda_fp16.h>
#include <math.h>

#define B_TOT  8192
#define SEQ    100
#define INF    15
#define HID    128
#define FUT    30
#define MROWS  32
#define NCTA   (B_TOT / MROWS)   // 256
#define NTHR   256
#define PH     136               // plane pitch (fp16); 272B rows -> conflict-free ldmatrix
#define PHB    272

// ---- weight fragment buffer: B-frag-layout packed, single fp16, PAIRED n-tiles ----
// chunk = 16 k's; per chunk: 32 n-tile-pairs x 32 lanes = 1024 uint4 entries
// entry = {nt0.r0, nt0.r1, nt1.r0, nt1.r1} for n-tiles (2*tp, 2*tp+1)
#define CHK    1024              // uint4 entries per chunk
#define WB_X   0                 // 1 chunk  (x projection, K=15 padded to 16)
#define WB_H0  (1  * CHK)        // 8 chunks (w_hh0)
#define WB_I1  (9  * CHK)        // 8 chunks (w_ih1)
#define WB_H1  (17 * CHK)        // 8 chunks (w_hh1)
#define WB_TOT (25 * CHK)
__device__ uint4 g_wb[WB_TOT];

// B frag (m16n8k16 col): reg r, half h -> element [k = r*8 + (lane%4)*2 + h][n = lane/4]
// n' (gate-interleaved) = ntile*8 + lane/4 ; j = n'>>2, g = n'&3 ; src row = g*128 + j
__global__ void pack_weights(const float* __restrict__ w_ih0,
                             const float* __restrict__ w_hh0,
                             const float* __restrict__ w_ih1,
                             const float* __restrict__ w_hh1) {
    int idx = blockIdx.x * blockDim.x + threadIdx.x;
    if (idx >= WB_TOT) return;
    int lane = idx & 31;
    int tp   = (idx >> 5) & 31;     // n-tile pair 0..31
    int cg   = idx >> 10;           // 0..24  (1024 entries per chunk)
    const float* W; int Ksrc; int lc;
    if      (cg == 0)  { W = w_ih0; Ksrc = INF; lc = 0; }
    else if (cg <= 8)  { W = w_hh0; Ksrc = HID; lc = cg - 1; }
    else if (cg <= 16) { W = w_ih1; Ksrc = HID; lc = cg - 9; }
    else               { W = w_hh1; Ksrc = HID; lc = cg - 17; }

    unsigned int u[4];
#pragma unroll
    for (int half = 0; half < 2; ++half) {
        int ntile = tp * 2 + half;
        int np = ntile * 8 + (lane >> 2);
        int j  = np >> 2;
        int g  = np & 3;
        int row = g * HID + j;
        for (int r = 0; r < 2; ++r) {
            unsigned short q[2];
            for (int h = 0; h < 2; ++h) {
                int k = lc * 16 + r * 8 + (lane & 3) * 2 + h;
                float v = (k < Ksrc) ? W[(size_t)row * Ksrc + k] : 0.0f;
                __half hv = __float2half_rn(v);
                q[h] = reinterpret_cast<unsigned short&>(hv);
            }
            u[half * 2 + r] = (unsigned int)q[0] | ((unsigned int)q[1] << 16);
        }
    }
    g_wb[idx] = make_uint4(u[0], u[1], u[2], u[3]);
}

// ---- PTX wrappers ----
__device__ __forceinline__ void ldsm4(unsigned int (&d)[4], unsigned int saddr) {
    asm volatile("ldmatrix.sync.aligned.m8n8.x4.shared.b16 {%0,%1,%2,%3}, [%4];"
                 : "=r"(d[0]), "=r"(d[1]), "=r"(d[2]), "=r"(d[3]) : "r"(saddr));
}
__device__ __forceinline__ void mma16816(float (&d)[4], const unsigned int (&a)[4],
                                         unsigned int b0, unsigned int b1) {
    asm volatile("mma.sync.aligned.m16n8k16.row.col.f32.f16.f16.f32 "
                 "{%0,%1,%2,%3},{%4,%5,%6,%7},{%8,%9},{%0,%1,%2,%3};"
                 : "+f"(d[0]), "+f"(d[1]), "+f"(d[2]), "+f"(d[3])
                 : "r"(a[0]), "r"(a[1]), "r"(a[2]), "r"(a[3]), "r"(b0), "r"(b1));
}

// ---- hardware-tanh activations: 1 MUFU each ----
__device__ __forceinline__ float tanha(float x) {
    float y; asm("tanh.approx.f32 %0, %1;" : "=f"(y) : "f"(x)); return y;
}
__device__ __forceinline__ float sigt(float x) {
    return fmaf(0.5f, tanha(0.5f * x), 0.5f);
}

// All planes 16B-aligned (ldmatrix requirement). c state lives in REGISTERS now.
struct __align__(16) Smem {
    alignas(16) float4 bias0[HID];
    alignas(16) float4 bias1[HID];
    alignas(16) float  fcw[2][HID];
    alignas(16) float  fcb[4];
    alignas(16) __half h0[2][MROWS * PH];
    alignas(16) __half h1[2][MROWS * PH];
    alignas(16) __half xp[MROWS * PH];      // x plane, SAME pitch as h planes
};

// One k16 chunk: A via ldmatrix (uniform pitch PHB), B via 4x LDG.128 (paired n-tiles).
__device__ __forceinline__ void gemm_chunk(float (&acc)[2][8][4],
                                           unsigned int shA, int k0,
                                           const uint4* __restrict__ wb,
                                           int ng, int lane) {
    unsigned int ah[2][4];
    const int rowOff = lane & 15;
    const int colB   = (k0 + ((lane >> 4) << 3)) * 2;
#pragma unroll
    for (int mt = 0; mt < 2; ++mt)
        ldsm4(ah[mt], shA + (unsigned int)((mt * 16 + rowOff) * PHB + colB));
    const uint4* wp = wb + (ng * 4) * 32 + lane;   // 4 n-tile-pairs per warp
#pragma unroll
    for (int tp = 0; tp < 4; ++tp) {
        uint4 w = __ldg(wp + tp * 32);
        mma16816(acc[0][2 * tp],     ah[0], w.x, w.y);
        mma16816(acc[1][2 * tp],     ah[1], w.x, w.y);
        mma16816(acc[0][2 * tp + 1], ah[0], w.z, w.w);
        mma16816(acc[1][2 * tp + 1], ah[1], w.z, w.w);
    }
}

// Gate epilogue: 2-shfl gather of (i,f,g,o) per (row,j), c update in REGISTERS,
// h write to fp16 plane (double-buffer target).
__device__ __forceinline__ void epilogue(float (&acc)[2][8][4], const float4* __restrict__ bias4,
                                         float (&creg)[16],
                                         __half* __restrict__ hplane,
                                         int ng, int lane) {
    const int odd = lane & 1;
#pragma unroll
    for (int mt = 0; mt < 2; ++mt) {
        const int row = mt * 16 + (lane >> 2) + (odd ? 8 : 0);
#pragma unroll
        for (int nt = 0; nt < 8; ++nt) {
            float d0 = acc[mt][nt][0], d1 = acc[mt][nt][1];
            float d2 = acc[mt][nt][2], d3 = acc[mt][nt][3];
            float s0 = odd ? d0 : d2;
            float s1 = odd ? d1 : d3;
            float r0 = __shfl_xor_sync(0xffffffffu, s0, 1);
            float r1 = __shfl_xor_sync(0xffffffffu, s1, 1);
            float gi = odd ? r0 : d0;
            float gf = odd ? r1 : d1;
            float gg = odd ? d2 : r0;
            float go = odd ? d3 : r1;
            int j = ng * 16 + nt * 2 + ((lane & 3) >> 1);
            float4 bb = bias4[j];
            gi += bb.x; gf += bb.y; gg += bb.z; go += bb.w;
            float c  = creg[mt * 8 + nt];
            float cn = sigt(gf) * c + sigt(gi) * tanha(gg);
            creg[mt * 8 + nt] = cn;
            float h = sigt(go) * tanha(cn);
            hplane[row * PH + j] = __float2half_rn(h);
        }
    }
}

__device__ __forceinline__ void zero_acc(float (&acc)[2][8][4]) {
#pragma unroll
    for (int mt = 0; mt < 2; ++mt)
#pragma unroll
        for (int nt = 0; nt < 8; ++nt)
#pragma unroll
            for (int q = 0; q < 4; ++q) acc[mt][nt][q] = 0.0f;
}

__global__ void __launch_bounds__(NTHR, 2)
lstm_traj_kernel(const float* __restrict__ x,
                 const float* __restrict__ b_ih0, const float* __restrict__ b_hh0,
                 const float* __restrict__ b_ih1, const float* __restrict__ b_hh1,
                 const float* __restrict__ fc_w, const float* __restrict__ fc_b,
                 float* __restrict__ out) {
    extern __shared__ char smraw[];
    Smem& sm = *reinterpret_cast<Smem*>(smraw);

    const int tid  = threadIdx.x;
    const int lane = tid & 31;
    const int ng   = tid >> 5;     // warp id = n-slice (j range [ng*16, ng*16+16))
    const int brow0 = blockIdx.x * MROWS;

    // ---- init ----
    for (int i = tid; i < 2 * MROWS * PH; i += NTHR) {
        sm.h0[0][i] = __float2half_rn(0.0f);
        sm.h1[0][i] = __float2half_rn(0.0f);
    }
    for (int i = tid; i < MROWS * PH; i += NTHR) sm.xp[i] = __float2half_rn(0.0f);
    if (tid < HID) {
        sm.bias0[tid] = make_float4(b_ih0[tid] + b_hh0[tid],
                                    b_ih0[HID + tid] + b_hh0[HID + tid],
                                    b_ih0[2 * HID + tid] + b_hh0[2 * HID + tid],
                                    b_ih0[3 * HID + tid] + b_hh0[3 * HID + tid]);
        sm.bias1[tid] = make_float4(b_ih1[tid] + b_hh1[tid],
                                    b_ih1[HID + tid] + b_hh1[HID + tid],
                                    b_ih1[2 * HID + tid] + b_hh1[2 * HID + tid],
                                    b_ih1[3 * HID + tid] + b_hh1[3 * HID + tid]);
    }
    if (tid < 2 * HID) (&sm.fcw[0][0])[tid] = fc_w[tid];
    if (tid < 2) sm.fcb[tid] = fc_b[tid];

    unsigned int shH0[2], shH1[2];
#pragma unroll
    for (int p = 0; p < 2; ++p) {
        shH0[p] = (unsigned int)__cvta_generic_to_shared(sm.h0[p]);
        shH1[p] = (unsigned int)__cvta_generic_to_shared(sm.h1[p]);
    }
    const unsigned int shX = (unsigned int)__cvta_generic_to_shared(sm.xp);

    float acc[2][8][4];
    float creg0[16], creg1[16];      // LSTM cell state, thread-private (fixed map)
#pragma unroll
    for (int i = 0; i < 16; ++i) { creg0[i] = 0.0f; creg1[i] = 0.0f; }

    for (int t = 0; t < SEQ + FUT; ++t) {
        const int p = t & 1;         // read buffer parity; write to p^1

        // stage x_t (encoder) as fp16
        if (t < SEQ) {
            for (int i = tid; i < MROWS * INF; i += NTHR) {
                int r = i / INF, c = i - r * INF;
                float v = x[(size_t)(brow0 + r) * (SEQ * INF) + (size_t)t * INF + c];
                sm.xp[r * PH + c] = __float2half_rn(v);
            }
        }
        __syncthreads();   // (A) x / feedback visible

        // ---- layer 0: [x | h0(p)] @ W^T -> h0(p^1) ----
        zero_acc(acc);
        gemm_chunk(acc, shX, 0, g_wb + WB_X, ng, lane);
#pragma unroll 1
        for (int c = 0; c < 8; ++c)
            gemm_chunk(acc, shH0[p], c * 16, g_wb + WB_H0 + c * CHK, ng, lane);
        epilogue(acc, sm.bias0, creg0, sm.h0[p ^ 1], ng, lane);
        __syncthreads();   // (C) new h0 visible

        // ---- layer 1: [h0(p^1) | h1(p)] @ W^T -> h1(p^1) ----
        zero_acc(acc);
#pragma unroll 1
        for (int c = 0; c < 8; ++c)
            gemm_chunk(acc, shH0[p ^ 1], c * 16, g_wb + WB_I1 + c * CHK, ng, lane);
#pragma unroll 1
        for (int c = 0; c < 8; ++c)
            gemm_chunk(acc, shH1[p], c * 16, g_wb + WB_H1 + c * CHK, ng, lane);
        epilogue(acc, sm.bias1, creg1, sm.h1[p ^ 1], ng, lane);
        __syncthreads();   // (E) new h1 visible

        // ---- decoder head ----
        if (t >= SEQ) {
            if (tid < 2 * MROWS) {
                int r = tid >> 1, o = tid & 1;
                float s = sm.fcb[o];
                const float* fw = &sm.fcw[o][0];
                const __half* hh = sm.h1[p ^ 1];
#pragma unroll 8
                for (int j = 0; j < HID; ++j)
                    s += __half2float(hh[r * PH + j]) * fw[j];
                out[(size_t)(brow0 + r) * (FUT * 2) + (size_t)(t - SEQ) * 2 + o] = s;
                sm.xp[r * PH + o] = __float2half_rn(s);   // feedback -> features 0:2
            }
            // next iteration's sync (A) publishes the feedback
        }
    }
}

extern "C" void kernel_launch(void* const* d_in, const int* in_sizes, int n_in,
                              void* d_out, int out_size) {
    const float* x     = (const float*)d_in[0];
    const float* w_ih0 = (const float*)d_in[1];
    const float* w_hh0 = (const float*)d_in[2];
    const float* b_ih0 = (const float*)d_in[3];
    const float* b_hh0 = (const float*)d_in[4];
    const float* w_ih1 = (const float*)d_in[5];
    const float* w_hh1 = (const float*)d_in[6];
    const float* b_ih1 = (const float*)d_in[7];
    const float* b_hh1 = (const float*)d_in[8];
    const float* fc_w  = (const float*)d_in[9];
    const float* fc_b  = (const float*)d_in[10];
    float* out = (float*)d_out;

    pack_weights<<<(WB_TOT + 255) / 256, 256>>>(w_ih0, w_hh0, w_ih1, w_hh1);

    cudaFuncSetAttribute(lstm_traj_kernel,
                         cudaFuncAttributeMaxDynamicSharedMemorySize,
                         (int)sizeof(Smem));
    lstm_traj_kernel<<<NCTA, NTHR, sizeof(Smem)>>>(
        x, b_ih0, b_hh0, b_ih1, b_hh1, fc_w, fc_b, out);
}

// round 16
// speedup vs baseline: 1.4673x; 1.4673x over previous
#include <cuda_runtime.h>
#include <cuda_fp16.h>
#include <math.h>

#define B_TOT  8192
#define SEQ    100
#define INF    15
#define HID    128
#define FUT    30
#define MROWS  32
#define NCTA   (B_TOT / MROWS)   // 256
#define NTHR   256
#define PH     136               // plane pitch (fp16); 272B rows -> conflict-free ldmatrix
#define PHB    272
#define CP     132               // c row pitch (fp32); MUST be >= 128 (j indexes 0..127)

// ---- weight fragment buffer: B-frag-layout packed, single fp16, PAIRED n-tiles ----
// chunk = 16 k's; per chunk: 32 n-tile-pairs x 32 lanes = 1024 uint4 entries
// entry = {nt0.r0, nt0.r1, nt1.r0, nt1.r1} for n-tiles (2*tp, 2*tp+1)
#define CHK    1024              // uint4 entries per chunk
#define WB_X   0                 // 1 chunk  (x projection, K=15 padded to 16)
#define WB_H0  (1  * CHK)        // 8 chunks (w_hh0)
#define WB_I1  (9  * CHK)        // 8 chunks (w_ih1)
#define WB_H1  (17 * CHK)        // 8 chunks (w_hh1)
#define WB_TOT (25 * CHK)
__device__ uint4 g_wb[WB_TOT];

// B frag (m16n8k16 col): reg r, half h -> element [k = r*8 + (lane%4)*2 + h][n = lane/4]
// n' (gate-interleaved) = ntile*8 + lane/4 ; j = n'>>2, g = n'&3 ; src row = g*128 + j
__global__ void pack_weights(const float* __restrict__ w_ih0,
                             const float* __restrict__ w_hh0,
                             const float* __restrict__ w_ih1,
                             const float* __restrict__ w_hh1) {
    int idx = blockIdx.x * blockDim.x + threadIdx.x;
    if (idx >= WB_TOT) return;
    int lane = idx & 31;
    int tp   = (idx >> 5) & 31;     // n-tile pair 0..31
    int cg   = idx >> 10;           // 0..24  (1024 entries per chunk)
    const float* W; int Ksrc; int lc;
    if      (cg == 0)  { W = w_ih0; Ksrc = INF; lc = 0; }
    else if (cg <= 8)  { W = w_hh0; Ksrc = HID; lc = cg - 1; }
    else if (cg <= 16) { W = w_ih1; Ksrc = HID; lc = cg - 9; }
    else               { W = w_hh1; Ksrc = HID; lc = cg - 17; }

    unsigned int u[4];
#pragma unroll
    for (int half = 0; half < 2; ++half) {
        int ntile = tp * 2 + half;
        int np = ntile * 8 + (lane >> 2);
        int j  = np >> 2;
        int g  = np & 3;
        int row = g * HID + j;
        for (int r = 0; r < 2; ++r) {
            unsigned short q[2];
            for (int h = 0; h < 2; ++h) {
                int k = lc * 16 + r * 8 + (lane & 3) * 2 + h;
                float v = (k < Ksrc) ? W[(size_t)row * Ksrc + k] : 0.0f;
                __half hv = __float2half_rn(v);
                q[h] = reinterpret_cast<unsigned short&>(hv);
            }
            u[half * 2 + r] = (unsigned int)q[0] | ((unsigned int)q[1] << 16);
        }
    }
    g_wb[idx] = make_uint4(u[0], u[1], u[2], u[3]);
}

// ---- PTX wrappers ----
__device__ __forceinline__ void ldsm4(unsigned int (&d)[4], unsigned int saddr) {
    asm volatile("ldmatrix.sync.aligned.m8n8.x4.shared.b16 {%0,%1,%2,%3}, [%4];"
                 : "=r"(d[0]), "=r"(d[1]), "=r"(d[2]), "=r"(d[3]) : "r"(saddr));
}
__device__ __forceinline__ void mma16816(float (&d)[4], const unsigned int (&a)[4],
                                         unsigned int b0, unsigned int b1) {
    asm volatile("mma.sync.aligned.m16n8k16.row.col.f32.f16.f16.f32 "
                 "{%0,%1,%2,%3},{%4,%5,%6,%7},{%8,%9},{%0,%1,%2,%3};"
                 : "+f"(d[0]), "+f"(d[1]), "+f"(d[2]), "+f"(d[3])
                 : "r"(a[0]), "r"(a[1]), "r"(a[2]), "r"(a[3]), "r"(b0), "r"(b1));
}

// ---- hardware-tanh activations: 1 MUFU each ----
__device__ __forceinline__ float tanha(float x) {
    float y; asm("tanh.approx.f32 %0, %1;" : "=f"(y) : "f"(x)); return y;
}
__device__ __forceinline__ float sigt(float x) {
    return fmaf(0.5f, tanha(0.5f * x), 0.5f);
}

// All planes 16B-aligned (ldmatrix requirement). c back in SMEM (R14-proven).
struct __align__(16) Smem {
    alignas(16) float4 bias0[HID];
    alignas(16) float4 bias1[HID];
    alignas(16) float  fcw[2][HID];
    alignas(16) float  fcb[4];
    alignas(16) float  c0[MROWS * CP + 4];
    alignas(16) float  c1[MROWS * CP + 4];
    alignas(16) __half h0[2][MROWS * PH];
    alignas(16) __half h1[2][MROWS * PH];
    alignas(16) __half xp[MROWS * PH];      // x plane, SAME pitch as h planes
};

// Load the 4 paired B-frag uint4s of one chunk for this warp's n-slice.
__device__ __forceinline__ void ld_b(uint4 (&b)[4], const uint4* __restrict__ wb,
                                     int ng, int lane) {
    const uint4* p = wb + (ng * 4) * 32 + lane;
#pragma unroll
    for (int tp = 0; tp < 4; ++tp) b[tp] = __ldg(p + tp * 32);
}

// Consume one k16 chunk: A via ldmatrix (uniform pitch PHB), B from registers.
__device__ __forceinline__ void mma_chunk(float (&acc)[2][8][4],
                                          unsigned int shA, int k0,
                                          const uint4 (&b)[4], int lane) {
    unsigned int ah[2][4];
    const int rowOff = lane & 15;
    const int colB   = (k0 + ((lane >> 4) << 3)) * 2;
#pragma unroll
    for (int mt = 0; mt < 2; ++mt)
        ldsm4(ah[mt], shA + (unsigned int)((mt * 16 + rowOff) * PHB + colB));
#pragma unroll
    for (int tp = 0; tp < 4; ++tp) {
        mma16816(acc[0][2 * tp],     ah[0], b[tp].x, b[tp].y);
        mma16816(acc[1][2 * tp],     ah[1], b[tp].x, b[tp].y);
        mma16816(acc[0][2 * tp + 1], ah[0], b[tp].z, b[tp].w);
        mma16816(acc[1][2 * tp + 1], ah[1], b[tp].z, b[tp].w);
    }
}

// Gate epilogue: 2-shfl gather of (i,f,g,o) per (row,j), c update (SMEM fp32),
// h write to fp16 plane (double-buffer target).
__device__ __forceinline__ void epilogue(float (&acc)[2][8][4], const float4* __restrict__ bias4,
                                         float* __restrict__ cplane,
                                         __half* __restrict__ hplane,
                                         int ng, int lane) {
    const int odd = lane & 1;
#pragma unroll
    for (int mt = 0; mt < 2; ++mt) {
        const int row = mt * 16 + (lane >> 2) + (odd ? 8 : 0);
#pragma unroll
        for (int nt = 0; nt < 8; ++nt) {
            float d0 = acc[mt][nt][0], d1 = acc[mt][nt][1];
            float d2 = acc[mt][nt][2], d3 = acc[mt][nt][3];
            float s0 = odd ? d0 : d2;
            float s1 = odd ? d1 : d3;
            float r0 = __shfl_xor_sync(0xffffffffu, s0, 1);
            float r1 = __shfl_xor_sync(0xffffffffu, s1, 1);
            float gi = odd ? r0 : d0;
            float gf = odd ? r1 : d1;
            float gg = odd ? d2 : r0;
            float go = odd ? d3 : r1;
            int j = ng * 16 + nt * 2 + ((lane & 3) >> 1);
            float4 bb = bias4[j];
            gi += bb.x; gf += bb.y; gg += bb.z; go += bb.w;
            float c  = cplane[row * CP + j];
            float cn = sigt(gf) * c + sigt(gi) * tanha(gg);
            cplane[row * CP + j] = cn;
            float h = sigt(go) * tanha(cn);
            hplane[row * PH + j] = __float2half_rn(h);
        }
    }
}

__device__ __forceinline__ void zero_acc(float (&acc)[2][8][4]) {
#pragma unroll
    for (int mt = 0; mt < 2; ++mt)
#pragma unroll
        for (int nt = 0; nt < 8; ++nt)
#pragma unroll
            for (int q = 0; q < 4; ++q) acc[mt][nt][q] = 0.0f;
}

__global__ void __launch_bounds__(NTHR, 2)
lstm_traj_kernel(const float* __restrict__ x,
                 const float* __restrict__ b_ih0, const float* __restrict__ b_hh0,
                 const float* __restrict__ b_ih1, const float* __restrict__ b_hh1,
                 const float* __restrict__ fc_w, const float* __restrict__ fc_b,
                 float* __restrict__ out) {
    extern __shared__ char smraw[];
    Smem& sm = *reinterpret_cast<Smem*>(smraw);

    const int tid  = threadIdx.x;
    const int lane = tid & 31;
    const int ng   = tid >> 5;     // warp id = n-slice (j range [ng*16, ng*16+16))
    const int brow0 = blockIdx.x * MROWS;

    // ---- init ----
    for (int i = tid; i < 2 * MROWS * PH; i += NTHR) {
        sm.h0[0][i] = __float2half_rn(0.0f);
        sm.h1[0][i] = __float2half_rn(0.0f);
    }
    for (int i = tid; i < MROWS * PH; i += NTHR) sm.xp[i] = __float2half_rn(0.0f);
    for (int i = tid; i < MROWS * CP; i += NTHR) { sm.c0[i] = 0.0f; sm.c1[i] = 0.0f; }
    if (tid < HID) {
        sm.bias0[tid] = make_float4(b_ih0[tid] + b_hh0[tid],
                                    b_ih0[HID + tid] + b_hh0[HID + tid],
                                    b_ih0[2 * HID + tid] + b_hh0[2 * HID + tid],
                                    b_ih0[3 * HID + tid] + b_hh0[3 * HID + tid]);
        sm.bias1[tid] = make_float4(b_ih1[tid] + b_hh1[tid],
                                    b_ih1[HID + tid] + b_hh1[HID + tid],
                                    b_ih1[2 * HID + tid] + b_hh1[2 * HID + tid],
                                    b_ih1[3 * HID + tid] + b_hh1[3 * HID + tid]);
    }
    if (tid < 2 * HID) (&sm.fcw[0][0])[tid] = fc_w[tid];
    if (tid < 2) sm.fcb[tid] = fc_b[tid];

    unsigned int shH0[2], shH1[2];
#pragma unroll
    for (int p = 0; p < 2; ++p) {
        shH0[p] = (unsigned int)__cvta_generic_to_shared(sm.h0[p]);
        shH1[p] = (unsigned int)__cvta_generic_to_shared(sm.h1[p]);
    }
    const unsigned int shX = (unsigned int)__cvta_generic_to_shared(sm.xp);

    float acc[2][8][4];
    uint4 b[2][4];

    ld_b(b[0], g_wb + WB_X, ng, lane);    // prime X-chunk weights for t=0

    for (int t = 0; t < SEQ + FUT; ++t) {
        const int p = t & 1;         // read buffer parity; write to p^1

        // stage x_t (encoder) as fp16
        if (t < SEQ) {
            for (int i = tid; i < MROWS * INF; i += NTHR) {
                int r = i / INF, c = i - r * INF;
                float v = x[(size_t)(brow0 + r) * (SEQ * INF) + (size_t)t * INF + c];
                sm.xp[r * PH + c] = __float2half_rn(v);
            }
        }
        __syncthreads();   // (A) x / feedback visible

        // ---- layer 0: 9 chunks (X, H0 x8), B pipelined one chunk ahead ----
        zero_acc(acc);
#pragma unroll
        for (int i = 0; i < 9; ++i) {
            if (i + 1 < 9)
                ld_b(b[(i + 1) & 1], g_wb + WB_H0 + i * CHK, ng, lane);
            unsigned int shA = (i == 0) ? shX : shH0[p];
            int k0 = (i == 0) ? 0 : (i - 1) * 16;
            mma_chunk(acc, shA, k0, b[i & 1], lane);
        }
        ld_b(b[0], g_wb + WB_I1, ng, lane);   // prime layer-1 (weights: barrier-free)
        epilogue(acc, sm.bias0, sm.c0, sm.h0[p ^ 1], ng, lane);
        __syncthreads();   // (C) new h0 visible

        // ---- layer 1: I1 x8 on h0(p^1), then H1 x8 on h1(p) ----
        zero_acc(acc);
#pragma unroll
        for (int i = 0; i < 8; ++i) {
            const uint4* nw = (i < 7) ? (g_wb + WB_I1 + (i + 1) * CHK) : (g_wb + WB_H1);
            ld_b(b[(i + 1) & 1], nw, ng, lane);
            mma_chunk(acc, shH0[p ^ 1], i * 16, b[i & 1], lane);
        }
#pragma unroll
        for (int i = 0; i < 8; ++i) {
            if (i + 1 < 8)
                ld_b(b[(i + 1) & 1], g_wb + WB_H1 + (i + 1) * CHK, ng, lane);
            mma_chunk(acc, shH1[p], i * 16, b[i & 1], lane);
        }
        ld_b(b[0], g_wb + WB_X, ng, lane);    // prime next step's X chunk
        epilogue(acc, sm.bias1, sm.c1, sm.h1[p ^ 1], ng, lane);
        __syncthreads();   // (E) new h1 visible

        // ---- decoder head ----
        if (t >= SEQ) {
            if (tid < 2 * MROWS) {
                int r = tid >> 1, o = tid & 1;
                float s = sm.fcb[o];
                const float* fw = &sm.fcw[o][0];
                const __half* hh = sm.h1[p ^ 1];
#pragma unroll 8
                for (int j = 0; j < HID; ++j)
                    s += __half2float(hh[r * PH + j]) * fw[j];
                out[(size_t)(brow0 + r) * (FUT * 2) + (size_t)(t - SEQ) * 2 + o] = s;
                sm.xp[r * PH + o] = __float2half_rn(s);   // feedback -> features 0:2
            }
            // next iteration's sync (A) publishes the feedback
        }
    }
}

extern "C" void kernel_launch(void* const* d_in, const int* in_sizes, int n_in,
                              void* d_out, int out_size) {
    const float* x     = (const float*)d_in[0];
    const float* w_ih0 = (const float*)d_in[1];
    const float* w_hh0 = (const float*)d_in[2];
    const float* b_ih0 = (const float*)d_in[3];
    const float* b_hh0 = (const float*)d_in[4];
    const float* w_ih1 = (const float*)d_in[5];
    const float* w_hh1 = (const float*)d_in[6];
    const float* b_ih1 = (const float*)d_in[7];
    const float* b_hh1 = (const float*)d_in[8];
    const float* fc_w  = (const float*)d_in[9];
    const float* fc_b  = (const float*)d_in[10];
    float* out = (float*)d_out;

    pack_weights<<<(WB_TOT + 255) / 256, 256>>>(w_ih0, w_hh0, w_ih1, w_hh1);

    cudaFuncSetAttribute(lstm_traj_kernel,
                         cudaFuncAttributeMaxDynamicSharedMemorySize,
                         (int)sizeof(Smem));
    lstm_traj_kernel<<<NCTA, NTHR, sizeof(Smem)>>>(
        x, b_ih0, b_hh0, b_ih1, b_hh1, fc_w, fc_b, out);
}